// round 12
// baseline (speedup 1.0000x reference)
#include <cuda_runtime.h>
#include <stdint.h>

#define N_V   100000
#define N_S   1000000

#define SPRING_Y  30000.0f
#define DASHPOT   100.0f
#define DT_F      5e-5f
#define NSTEP     100

#define NBLK  296                       // 2 CTAs per SM
#define NTHR  512                       // 16 warps/block
#define WPB   (NTHR / 32)               // 16
#define N_VP  (NBLK * NTHR)             // 151552 slots
#define NWARP (N_VP / 32)               // 4736
#define MAXD  2048                      // bins: [0,512) split region, [512,2048) unsplit
#define DEG_CAP 22                      // deg > DEG_CAP gets split into 2 slots
#define ENT_CAP (2 * N_S + 262144)
#define CAP_EDGES 10240                 // per-block smem edge capacity (x8B = 80 KB)

#define F_SPLIT (1 << 30)
#define F_SEC   (1 << 29)
#define V_MASK  0x0FFFFFFF
#define VB_SPLIT (1 << 30)
#define VB_MASK  (VB_SPLIT - 1)

// ---------------- device scratch (no allocation allowed) -------------------
__device__ float4 g_rec0[N_V];          // {x.x, x.y, x.z, packed v (3xs8 + exp byte)}
__device__ float4 g_rec1[N_V];
__device__ float  g_invm[N_V];
__device__ int    g_deg[N_V];
__device__ int    g_hist[MAXD];
__device__ int    g_binoff[MAXD];
__device__ int    g_perm[N_VP];         // encoded vertex (flags) or -1
__device__ int    g_sdeg[N_VP];         // per-slot edge count
__device__ int    g_spos[N_V];          // primary slot of vertex
__device__ int    g_vbase[N_V];         // entry base addr | VB_SPLIT flag
__device__ int    g_wdeg[NWARP];
__device__ int    g_wbase[NWARP + 1];
__device__ int    g_fill[N_V];
__device__ int2   g_ent[ENT_CAP];       // {other_vertex, bitcast(SPRING_Y/rest)}

// ---------------- software grid barrier (atomic counter) --------------------
__device__ unsigned g_bar_count = 0;
__device__ volatile unsigned g_bar_gen = 0;

__device__ __forceinline__ void grid_sync() {
    __syncthreads();
    if (threadIdx.x == 0) {
        unsigned gen = g_bar_gen;
        __threadfence();
        unsigned t = atomicAdd(&g_bar_count, 1u);
        if (t == NBLK - 1) {
            g_bar_count = 0;
            __threadfence();
            g_bar_gen = gen + 1;
        } else {
            while (g_bar_gen == gen) { __nanosleep(32); }
        }
        __threadfence();
    }
    __syncthreads();
}

// ---------------- velocity pack/unpack --------------------------------------
__device__ __forceinline__ unsigned pack_v(float vx, float vy, float vz) {
    float m = fmaxf(fmaxf(fabsf(vx), fabsf(vy)), fabsf(vz));
    int eb = (__float_as_int(m) >> 23) & 0xFF;
    float inv = __int_as_float((253 - eb) << 23) * 127.0f;   // 127 * 2^(126-eb)
    int qx = __float2int_rn(vx * inv);
    int qy = __float2int_rn(vy * inv);
    int qz = __float2int_rn(vz * inv);
    return (unsigned)(qx & 0xFF) | ((unsigned)(qy & 0xFF) << 8) |
           ((unsigned)(qz & 0xFF) << 16) | ((unsigned)eb << 24);
}

__device__ __forceinline__ void unpack_v(unsigned u, float& vx, float& vy, float& vz) {
    int qx = ((int)(u << 24)) >> 24;
    int qy = ((int)(u << 16)) >> 24;
    int qz = ((int)(u << 8))  >> 24;
    int eb = (int)(u >> 24);
    float s = __int_as_float((eb + 1) << 23) * (1.0f / 127.0f);
    vx = (float)qx * s;
    vy = (float)qy * s;
    vz = (float)qz * s;
}

// ---------------- force accumulation body ------------------------------------
__device__ __forceinline__ void edge_force(int2 ent, const float4* __restrict__ cur,
                                           float xi_x, float xi_y, float xi_z,
                                           float vi_x, float vi_y, float vi_z,
                                           float& fx, float& fy, float& fz) {
    float  kor = __int_as_float(ent.y);
    float4 ro  = __ldg(&cur[ent.x]);

    float vox, voy, voz;
    unpack_v(__float_as_uint(ro.w), vox, voy, voz);

    float dx = ro.x - xi_x;
    float dy = ro.y - xi_y;
    float dz = ro.z - xi_z;

    float len2   = dx*dx + dy*dy + dz*dz;
    float invlen = rsqrtf(len2);
    float len    = len2 * invlen;

    float c    = kor * len - SPRING_Y;
    float vrel = ((vox - vi_x)*dx + (voy - vi_y)*dy + (voz - vi_z)*dz) * invlen;
    float s    = (c + DASHPOT * vrel) * invlen;

    fx += s * dx;
    fy += s * dy;
    fz += s * dz;
}

// ---------------- bin mapping ------------------------------------------------
__device__ __forceinline__ int bin_of(int d) {
    if (d > DEG_CAP) {
        int e = (d + 1) >> 1;
        if (e > 511) e = 511;
        return 511 - e;                 // split region: bins [0,512), high e first
    }
    return 512 + (1023 - d);            // unsplit region after, high d first
}

// ---------------- prep kernels ----------------------------------------------
__global__ void __launch_bounds__(256) k_clear() {
    int i = blockIdx.x * blockDim.x + threadIdx.x;
    if (i < N_V)  { g_deg[i] = 0; g_fill[i] = 0; }
    if (i < MAXD) { g_hist[i] = 0; }
    if (i < N_VP) { g_perm[i] = -1; g_sdeg[i] = 0; }
}

__global__ void __launch_bounds__(256) k_count(const int4* __restrict__ sp2) {
    int i = blockIdx.x * blockDim.x + threadIdx.x;
    if (i >= N_S / 2) return;
    int4 s = sp2[i];                    // two springs per thread
    atomicAdd(&g_deg[s.x], 1);
    atomicAdd(&g_deg[s.y], 1);
    atomicAdd(&g_deg[s.z], 1);
    atomicAdd(&g_deg[s.w], 1);
}

__global__ void __launch_bounds__(256) k_hist() {
    int i = blockIdx.x * blockDim.x + threadIdx.x;
    if (i >= N_V) return;
    int d = g_deg[i];
    atomicAdd(&g_hist[bin_of(d)], (d > DEG_CAP) ? 2 : 1);
}

__global__ void __launch_bounds__(1024) k_scan_bins() {   // single block, MAXD bins
    __shared__ int part[1024];
    const int t  = threadIdx.x;
    const int CH = MAXD / 1024;
    int beg = t * CH, end = beg + CH;
    int s = 0;
    for (int i = beg; i < end; ++i) s += g_hist[i];
    part[t] = s;
    __syncthreads();
    for (int d = 1; d < 1024; d <<= 1) {
        int v = (t >= d) ? part[t - d] : 0;
        __syncthreads();
        part[t] += v;
        __syncthreads();
    }
    int run = (t > 0) ? part[t - 1] : 0;
    for (int i = beg; i < end; ++i) {
        g_binoff[i] = run;
        run += g_hist[i];
    }
}

__global__ void __launch_bounds__(256) k_scatter() {
    int v = blockIdx.x * blockDim.x + threadIdx.x;
    if (v >= N_V) return;
    int d = g_deg[v];
    int b = bin_of(d);
    if (d > DEG_CAP) {
        int p = atomicAdd(&g_binoff[b], 2);         // even-aligned pair
        g_perm[p]     = v | F_SPLIT;
        g_perm[p + 1] = v | F_SPLIT | F_SEC;
        g_sdeg[p]     = (d + 1) >> 1;
        g_sdeg[p + 1] = d >> 1;
        g_spos[v] = p;
    } else {
        int p = atomicAdd(&g_binoff[b], 1);
        g_perm[p] = v;
        g_sdeg[p] = d;
        g_spos[v] = p;
    }
}

__global__ void __launch_bounds__(256) k_wdeg() {
    int w = blockIdx.x * blockDim.x + threadIdx.x;
    if (w >= NWARP) return;
    int mx = 0;
    #pragma unroll 8
    for (int l = 0; l < 32; ++l) {
        int d = g_sdeg[w * 32 + l];
        if (d > mx) mx = d;
    }
    g_wdeg[w] = mx;
}

__global__ void __launch_bounds__(1024) k_scan_warps() {  // single block over NWARP
    __shared__ int part[1024];
    const int t  = threadIdx.x;
    const int CH = (NWARP + 1023) / 1024;
    int beg = t * CH, end = beg + CH;
    if (end > NWARP) end = NWARP;
    if (beg > NWARP) beg = NWARP;
    int s = 0;
    for (int i = beg; i < end; ++i) s += 32 * g_wdeg[i];
    part[t] = s;
    __syncthreads();
    for (int d = 1; d < 1024; d <<= 1) {
        int v = (t >= d) ? part[t - d] : 0;
        __syncthreads();
        part[t] += v;
        __syncthreads();
    }
    int run = (t > 0) ? part[t - 1] : 0;
    for (int i = beg; i < end; ++i) {
        g_wbase[i] = run;
        run += 32 * g_wdeg[i];
    }
    if (t == 1023) g_wbase[NWARP] = part[1023];
}

__global__ void __launch_bounds__(256) k_vbase() {
    int v = blockIdx.x * blockDim.x + threadIdx.x;
    if (v >= N_V) return;
    int p = g_spos[v];
    int base = g_wbase[p >> 5] + (p & 31);
    g_vbase[v] = base | ((g_deg[v] > DEG_CAP) ? VB_SPLIT : 0);
}

__global__ void __launch_bounds__(256) k_fill(const int2* __restrict__ sp,
                                              const float* __restrict__ rest) {
    int i = blockIdx.x * blockDim.x + threadIdx.x;
    if (i >= N_S) return;
    int2  s  = sp[i];
    int   kb = __float_as_int(SPRING_Y / rest[i]);
    #pragma unroll
    for (int e = 0; e < 2; ++e) {
        int u     = e ? s.y : s.x;
        int other = e ? s.x : s.y;
        int vb   = g_vbase[u];
        int base = vb & VB_MASK;
        int k    = atomicAdd(&g_fill[u], 1);
        int addr = (vb & VB_SPLIT) ? (base + (k >> 1) * 32 + (k & 1))
                                   : (base + k * 32);
        g_ent[addr] = make_int2(other, kb);
    }
}

__global__ void __launch_bounds__(256) k_init(const float* __restrict__ x,
                                              const float* __restrict__ m) {
    int i = blockIdx.x * blockDim.x + threadIdx.x;
    if (i >= N_V) return;
    g_rec0[i] = make_float4(x[3*i+0], x[3*i+1], x[3*i+2], __int_as_float(0));
    g_invm[i] = 1.0f / m[i];
}

// ---------------- persistent fused simulation -------------------------------
__global__ void __launch_bounds__(NTHR, 2) k_sim(float* __restrict__ out) {
    extern __shared__ int2 s_ent[];            // staged edge lists
    __shared__ int s_size[WPB], s_off[WPB + 1];

    const int lane = threadIdx.x & 31;
    const int j    = threadIdx.x >> 5;                 // warp-in-block (0..15)
    const int swarp = j * NBLK + blockIdx.x;           // round-robin dealt warp rank
    const int slot  = swarp * 32 + lane;
    const float drag = expf(-DT_F * 1.0f);

    const int  enc   = g_perm[slot];
    const bool valid = enc >= 0;
    const int  v     = enc & V_MASK;
    const bool split = valid && (enc & F_SPLIT);
    const bool sec   = valid && (enc & F_SEC);
    const bool owner = valid && !sec;

    int deg = valid ? g_sdeg[slot] : 0;
    float xi_x = 0, xi_y = 0, xi_z = 0, vi_x = 0, vi_y = 0, vi_z = 0, im = 0;
    if (valid) {
        float4 r = g_rec0[v];
        xi_x = r.x; xi_y = r.y; xi_z = r.z;
        im   = g_invm[v];
    }

    // ---- stage this block's edge lists into shared memory (once) ----
    const int gbase = g_wbase[swarp];
    const int wsz   = 32 * g_wdeg[swarp];
    if (lane == 0) s_size[j] = wsz;
    __syncthreads();
    if (threadIdx.x == 0) {
        int r = 0;
        for (int q = 0; q < WPB; ++q) { s_off[q] = r; r += s_size[q]; }
        s_off[WPB] = r;
    }
    __syncthreads();
    const int  soff     = s_off[j];
    const bool use_smem = (soff + wsz) <= CAP_EDGES;
    if (use_smem) {
        for (int t = lane; t < wsz; t += 32) s_ent[soff + t] = g_ent[gbase + t];
    }
    __syncthreads();

    const float4* cur = g_rec0;
    float4*       nxt = g_rec1;

    for (int step = 0; step < NSTEP; ++step) {
        float fx = 0.0f, fy = 0.0f, fz = 0.0f;

        if (use_smem) {
            const int2* ep = &s_ent[soff + lane];
            #pragma unroll 4
            for (int k = 0; k < deg; ++k)
                edge_force(ep[k << 5], cur, xi_x, xi_y, xi_z, vi_x, vi_y, vi_z, fx, fy, fz);
        } else {
            const int2* ep = &g_ent[gbase + lane];
            #pragma unroll 4
            for (int k = 0; k < deg; ++k)
                edge_force(__ldg(&ep[k << 5]), cur, xi_x, xi_y, xi_z, vi_x, vi_y, vi_z, fx, fy, fz);
        }

        // combine split pairs: secondary sits at lane+1 of same warp
        {
            float ox = __shfl_down_sync(0xffffffffu, fx, 1);
            float oy = __shfl_down_sync(0xffffffffu, fy, 1);
            float oz = __shfl_down_sync(0xffffffffu, fz, 1);
            if (split && !sec) { fx += ox; fy += oy; fz += oz; }
        }

        if (owner) {
            vi_x = (vi_x + DT_F * (fx * im)) * drag;
            vi_y = (vi_y + DT_F * (fy * im)) * drag;
            vi_z = (vi_z + DT_F * (fz * im - 9.8f)) * drag;

            xi_x += DT_F * vi_x;
            xi_y += DT_F * vi_y;
            xi_z += DT_F * vi_z;

            xi_z = fmaxf(xi_z, 0.0f);
            if (xi_z == 0.0f) vi_z = 0.0f;

            nxt[v] = make_float4(xi_x, xi_y, xi_z,
                                 __uint_as_float(pack_v(vi_x, vi_y, vi_z)));
        }

        // propagate updated state owner -> secondary via in-warp shuffle
        {
            float nx0 = __shfl_up_sync(0xffffffffu, xi_x, 1);
            float nx1 = __shfl_up_sync(0xffffffffu, xi_y, 1);
            float nx2 = __shfl_up_sync(0xffffffffu, xi_z, 1);
            float nv0 = __shfl_up_sync(0xffffffffu, vi_x, 1);
            float nv1 = __shfl_up_sync(0xffffffffu, vi_y, 1);
            float nv2 = __shfl_up_sync(0xffffffffu, vi_z, 1);
            if (sec) {
                xi_x = nx0; xi_y = nx1; xi_z = nx2;
                vi_x = nv0; vi_y = nv1; vi_z = nv2;
            }
        }

        if (step + 1 < NSTEP) {
            grid_sync();
            const float4* t = cur; cur = nxt; nxt = (float4*)t;
        }
    }

    if (owner) {
        out[3*v+0] = xi_x;
        out[3*v+1] = xi_y;
        out[3*v+2] = xi_z;
    }
}

// ---------------- launch ----------------------------------------------------
extern "C" void kernel_launch(void* const* d_in, const int* in_sizes, int n_in,
                              void* d_out, int out_size) {
    const float* x0   = (const float*)d_in[0];   // [N_V, 3] f32
    const int2*  sp   = (const int2*) d_in[1];   // [N_S, 2] i32
    const float* rest = (const float*)d_in[2];   // [N_S]    f32
    const float* mass = (const float*)d_in[3];   // [N_V]    f32
    float*       out  = (float*)d_out;

    const size_t smem = (size_t)CAP_EDGES * sizeof(int2);
    cudaFuncSetAttribute(k_sim, cudaFuncAttributeMaxDynamicSharedMemorySize, (int)smem);

    const int TB = 256;
    k_clear     <<<(N_VP + TB - 1) / TB, TB>>>();
    k_count     <<<(N_S / 2 + TB - 1) / TB, TB>>>((const int4*)sp);
    k_hist      <<<(N_V + TB - 1) / TB, TB>>>();
    k_scan_bins <<<1, 1024>>>();
    k_scatter   <<<(N_V + TB - 1) / TB, TB>>>();
    k_wdeg      <<<(NWARP + TB - 1) / TB, TB>>>();
    k_scan_warps<<<1, 1024>>>();
    k_vbase     <<<(N_V + TB - 1) / TB, TB>>>();
    k_fill      <<<(N_S + TB - 1) / TB, TB>>>(sp, rest);
    k_init      <<<(N_V + TB - 1) / TB, TB>>>(x0, mass);
    k_sim       <<<NBLK, NTHR, smem>>>(out);
}

// round 13
// speedup vs baseline: 1.0154x; 1.0154x over previous
#include <cuda_runtime.h>
#include <stdint.h>

#define N_V   100000
#define N_S   1000000

#define SPRING_Y  30000.0f
#define DASHPOT   100.0f
#define DT_F      5e-5f
#define NSTEP     100

#define NBLK  296                       // 2 CTAs per SM
#define NTHR  512                       // 16 warps/block
#define WPB   (NTHR / 32)               // 16
#define N_VP  (NBLK * NTHR)             // 151552 slots
#define NWARP (N_VP / 32)               // 4736
#define MAXD  2048                      // bins: [0,512) split region, [512,2048) unsplit
#define DEG_CAP 22                      // deg > DEG_CAP gets split into 2 slots
#define ENT_CAP (2 * N_S + 262144)
#define CAP_EDGES 10240                 // per-block smem edge capacity (x8B = 80 KB)

#define F_SPLIT (1 << 30)
#define F_SEC   (1 << 29)
#define V_MASK  0x0FFFFFFF
#define VB_SPLIT (1 << 30)
#define VB_MASK  (VB_SPLIT - 1)

// ---------------- device scratch (no allocation allowed) -------------------
__device__ float4 g_rec0[N_VP];         // slot-ordered {x, v-packed} records
__device__ float4 g_rec1[N_VP];
__device__ float  g_im[N_VP];           // slot-ordered 1/mass
__device__ int    g_deg[N_V];
__device__ int    g_hist[MAXD];
__device__ int    g_binoff[MAXD];
__device__ int    g_perm[N_VP];         // encoded vertex (flags) or -1
__device__ int    g_sdeg[N_VP];         // per-slot edge count
__device__ int    g_spos[N_V];          // primary slot of vertex
__device__ int    g_vbase[N_V];         // entry base addr | VB_SPLIT flag
__device__ int    g_wdeg[NWARP];
__device__ int    g_wbase[NWARP + 1];
__device__ int    g_fill[N_V];
__device__ int2   g_ent[ENT_CAP];       // {other PRIMARY SLOT, bitcast(SPRING_Y/rest)}

// ---------------- software grid barrier (atomic counter) --------------------
__device__ unsigned g_bar_count = 0;
__device__ volatile unsigned g_bar_gen = 0;

__device__ __forceinline__ void grid_sync() {
    __syncthreads();
    if (threadIdx.x == 0) {
        unsigned gen = g_bar_gen;
        __threadfence();
        unsigned t = atomicAdd(&g_bar_count, 1u);
        if (t == NBLK - 1) {
            g_bar_count = 0;
            __threadfence();
            g_bar_gen = gen + 1;
        } else {
            while (g_bar_gen == gen) { __nanosleep(32); }
        }
        __threadfence();
    }
    __syncthreads();
}

// ---------------- velocity pack/unpack --------------------------------------
__device__ __forceinline__ unsigned pack_v(float vx, float vy, float vz) {
    float m = fmaxf(fmaxf(fabsf(vx), fabsf(vy)), fabsf(vz));
    int eb = (__float_as_int(m) >> 23) & 0xFF;
    float inv = __int_as_float((253 - eb) << 23) * 127.0f;   // 127 * 2^(126-eb)
    int qx = __float2int_rn(vx * inv);
    int qy = __float2int_rn(vy * inv);
    int qz = __float2int_rn(vz * inv);
    return (unsigned)(qx & 0xFF) | ((unsigned)(qy & 0xFF) << 8) |
           ((unsigned)(qz & 0xFF) << 16) | ((unsigned)eb << 24);
}

__device__ __forceinline__ void unpack_v(unsigned u, float& vx, float& vy, float& vz) {
    int qx = ((int)(u << 24)) >> 24;
    int qy = ((int)(u << 16)) >> 24;
    int qz = ((int)(u << 8))  >> 24;
    int eb = (int)(u >> 24);
    float s = __int_as_float((eb + 1) << 23) * (1.0f / 127.0f);
    vx = (float)qx * s;
    vy = (float)qy * s;
    vz = (float)qz * s;
}

// ---------------- force accumulation body ------------------------------------
__device__ __forceinline__ void edge_force(int2 ent, const float4* __restrict__ cur,
                                           float xi_x, float xi_y, float xi_z,
                                           float vi_x, float vi_y, float vi_z,
                                           float& fx, float& fy, float& fz) {
    float  kor = __int_as_float(ent.y);
    float4 ro  = __ldg(&cur[ent.x]);      // ent.x = neighbor's primary slot

    float vox, voy, voz;
    unpack_v(__float_as_uint(ro.w), vox, voy, voz);

    float dx = ro.x - xi_x;
    float dy = ro.y - xi_y;
    float dz = ro.z - xi_z;

    float len2   = dx*dx + dy*dy + dz*dz;
    float invlen = rsqrtf(len2);
    float len    = len2 * invlen;

    float c    = kor * len - SPRING_Y;
    float vrel = ((vox - vi_x)*dx + (voy - vi_y)*dy + (voz - vi_z)*dz) * invlen;
    float s    = (c + DASHPOT * vrel) * invlen;

    fx += s * dx;
    fy += s * dy;
    fz += s * dz;
}

// ---------------- bin mapping ------------------------------------------------
__device__ __forceinline__ int bin_of(int d) {
    if (d > DEG_CAP) {
        int e = (d + 1) >> 1;
        if (e > 511) e = 511;
        return 511 - e;                 // split region: bins [0,512), high e first
    }
    return 512 + (1023 - d);            // unsplit region after, high d first
}

// ---------------- prep kernels ----------------------------------------------
__global__ void __launch_bounds__(256) k_clear() {
    int i = blockIdx.x * blockDim.x + threadIdx.x;
    if (i < N_V)  { g_deg[i] = 0; g_fill[i] = 0; }
    if (i < MAXD) { g_hist[i] = 0; }
    if (i < N_VP) { g_perm[i] = -1; g_sdeg[i] = 0; }
}

__global__ void __launch_bounds__(256) k_count(const int4* __restrict__ sp2) {
    int i = blockIdx.x * blockDim.x + threadIdx.x;
    if (i >= N_S / 2) return;
    int4 s = sp2[i];
    atomicAdd(&g_deg[s.x], 1);
    atomicAdd(&g_deg[s.y], 1);
    atomicAdd(&g_deg[s.z], 1);
    atomicAdd(&g_deg[s.w], 1);
}

__global__ void __launch_bounds__(256) k_hist() {
    int i = blockIdx.x * blockDim.x + threadIdx.x;
    if (i >= N_V) return;
    int d = g_deg[i];
    atomicAdd(&g_hist[bin_of(d)], (d > DEG_CAP) ? 2 : 1);
}

__global__ void __launch_bounds__(1024) k_scan_bins() {   // single block, MAXD bins
    __shared__ int part[1024];
    const int t  = threadIdx.x;
    const int CH = MAXD / 1024;
    int beg = t * CH, end = beg + CH;
    int s = 0;
    for (int i = beg; i < end; ++i) s += g_hist[i];
    part[t] = s;
    __syncthreads();
    for (int d = 1; d < 1024; d <<= 1) {
        int v = (t >= d) ? part[t - d] : 0;
        __syncthreads();
        part[t] += v;
        __syncthreads();
    }
    int run = (t > 0) ? part[t - 1] : 0;
    for (int i = beg; i < end; ++i) {
        g_binoff[i] = run;
        run += g_hist[i];
    }
}

__global__ void __launch_bounds__(256) k_scatter() {
    int v = blockIdx.x * blockDim.x + threadIdx.x;
    if (v >= N_V) return;
    int d = g_deg[v];
    int b = bin_of(d);
    if (d > DEG_CAP) {
        int p = atomicAdd(&g_binoff[b], 2);         // even-aligned pair
        g_perm[p]     = v | F_SPLIT;
        g_perm[p + 1] = v | F_SPLIT | F_SEC;
        g_sdeg[p]     = (d + 1) >> 1;
        g_sdeg[p + 1] = d >> 1;
        g_spos[v] = p;
    } else {
        int p = atomicAdd(&g_binoff[b], 1);
        g_perm[p] = v;
        g_sdeg[p] = d;
        g_spos[v] = p;
    }
}

__global__ void __launch_bounds__(256) k_wdeg() {
    int w = blockIdx.x * blockDim.x + threadIdx.x;
    if (w >= NWARP) return;
    int mx = 0;
    #pragma unroll 8
    for (int l = 0; l < 32; ++l) {
        int d = g_sdeg[w * 32 + l];
        if (d > mx) mx = d;
    }
    g_wdeg[w] = mx;
}

__global__ void __launch_bounds__(1024) k_scan_warps() {  // single block over NWARP
    __shared__ int part[1024];
    const int t  = threadIdx.x;
    const int CH = (NWARP + 1023) / 1024;
    int beg = t * CH, end = beg + CH;
    if (end > NWARP) end = NWARP;
    if (beg > NWARP) beg = NWARP;
    int s = 0;
    for (int i = beg; i < end; ++i) s += 32 * g_wdeg[i];
    part[t] = s;
    __syncthreads();
    for (int d = 1; d < 1024; d <<= 1) {
        int v = (t >= d) ? part[t - d] : 0;
        __syncthreads();
        part[t] += v;
        __syncthreads();
    }
    int run = (t > 0) ? part[t - 1] : 0;
    for (int i = beg; i < end; ++i) {
        g_wbase[i] = run;
        run += 32 * g_wdeg[i];
    }
    if (t == 1023) g_wbase[NWARP] = part[1023];
}

__global__ void __launch_bounds__(256) k_vbase() {
    int v = blockIdx.x * blockDim.x + threadIdx.x;
    if (v >= N_V) return;
    int p = g_spos[v];
    int base = g_wbase[p >> 5] + (p & 31);
    g_vbase[v] = base | ((g_deg[v] > DEG_CAP) ? VB_SPLIT : 0);
}

__global__ void __launch_bounds__(256) k_fill(const int2* __restrict__ sp,
                                              const float* __restrict__ rest) {
    int i = blockIdx.x * blockDim.x + threadIdx.x;
    if (i >= N_S) return;
    int2  s  = sp[i];
    int   kb = __float_as_int(SPRING_Y / rest[i]);
    int   px = g_spos[s.x];
    int   py = g_spos[s.y];
    #pragma unroll
    for (int e = 0; e < 2; ++e) {
        int u      = e ? s.y : s.x;
        int oslot  = e ? px  : py;      // neighbor's primary slot
        int vb   = g_vbase[u];
        int base = vb & VB_MASK;
        int k    = atomicAdd(&g_fill[u], 1);
        int addr = (vb & VB_SPLIT) ? (base + (k >> 1) * 32 + (k & 1))
                                   : (base + k * 32);
        g_ent[addr] = make_int2(oslot, kb);
    }
}

__global__ void __launch_bounds__(256) k_init(const float* __restrict__ x,
                                              const float* __restrict__ m) {
    int v = blockIdx.x * blockDim.x + threadIdx.x;
    if (v >= N_V) return;
    float4 rec = make_float4(x[3*v+0], x[3*v+1], x[3*v+2], __int_as_float(0));
    float  im  = 1.0f / m[v];
    int p = g_spos[v];
    g_rec0[p] = rec;
    g_im[p]   = im;
    if (g_deg[v] > DEG_CAP) {          // secondary slot also needs initial state
        g_rec0[p + 1] = rec;
        g_im[p + 1]   = im;
    }
}

// ---------------- persistent fused simulation -------------------------------
__global__ void __launch_bounds__(NTHR, 2) k_sim(float* __restrict__ out) {
    extern __shared__ int2 s_ent[];            // staged edge lists
    __shared__ int s_size[WPB], s_off[WPB + 1];

    const int lane = threadIdx.x & 31;
    const int j    = threadIdx.x >> 5;                 // warp-in-block (0..15)
    const int swarp = j * NBLK + blockIdx.x;           // round-robin dealt warp rank
    const int slot  = swarp * 32 + lane;
    const float drag = expf(-DT_F * 1.0f);

    const int  enc   = g_perm[slot];
    const bool valid = enc >= 0;
    const int  v     = enc & V_MASK;
    const bool split = valid && (enc & F_SPLIT);
    const bool sec   = valid && (enc & F_SEC);
    const bool owner = valid && !sec;
    const bool warp_has_split = __ballot_sync(0xffffffffu, split) != 0;

    int deg = valid ? g_sdeg[slot] : 0;
    float4 r0 = g_rec0[slot];                          // coalesced (slot order)
    float xi_x = r0.x, xi_y = r0.y, xi_z = r0.z;
    float vi_x = 0, vi_y = 0, vi_z = 0;
    float im = g_im[slot];

    // ---- stage this block's edge lists into shared memory (once) ----
    const int gbase = g_wbase[swarp];
    const int wsz   = 32 * g_wdeg[swarp];
    if (lane == 0) s_size[j] = wsz;
    __syncthreads();
    if (threadIdx.x == 0) {
        int r = 0;
        for (int q = 0; q < WPB; ++q) { s_off[q] = r; r += s_size[q]; }
        s_off[WPB] = r;
    }
    __syncthreads();
    const int  soff     = s_off[j];
    const bool use_smem = (soff + wsz) <= CAP_EDGES;
    if (use_smem) {
        for (int t = lane; t < wsz; t += 32) s_ent[soff + t] = g_ent[gbase + t];
    }
    __syncthreads();

    const float4* cur = g_rec0;
    float4*       nxt = g_rec1;

    for (int step = 0; step < NSTEP; ++step) {
        float fx = 0.0f, fy = 0.0f, fz = 0.0f;

        if (use_smem) {
            const int2* ep = &s_ent[soff + lane];
            #pragma unroll 4
            for (int k = 0; k < deg; ++k)
                edge_force(ep[k << 5], cur, xi_x, xi_y, xi_z, vi_x, vi_y, vi_z, fx, fy, fz);
        } else {
            const int2* ep = &g_ent[gbase + lane];
            #pragma unroll 4
            for (int k = 0; k < deg; ++k)
                edge_force(__ldg(&ep[k << 5]), cur, xi_x, xi_y, xi_z, vi_x, vi_y, vi_z, fx, fy, fz);
        }

        if (warp_has_split) {
            // combine split pairs: secondary sits at lane+1 of same warp
            float ox = __shfl_down_sync(0xffffffffu, fx, 1);
            float oy = __shfl_down_sync(0xffffffffu, fy, 1);
            float oz = __shfl_down_sync(0xffffffffu, fz, 1);
            if (split && !sec) { fx += ox; fy += oy; fz += oz; }
        }

        // integrate (owners; harmless for others - they don't store)
        vi_x = (vi_x + DT_F * (fx * im)) * drag;
        vi_y = (vi_y + DT_F * (fy * im)) * drag;
        vi_z = (vi_z + DT_F * (fz * im - 9.8f)) * drag;

        xi_x += DT_F * vi_x;
        xi_y += DT_F * vi_y;
        xi_z += DT_F * vi_z;

        xi_z = fmaxf(xi_z, 0.0f);
        if (xi_z == 0.0f) vi_z = 0.0f;

        if (warp_has_split) {
            // secondary integrated garbage (its force half alone); replace with
            // owner's correct state from lane-1
            float nx0 = __shfl_up_sync(0xffffffffu, xi_x, 1);
            float nx1 = __shfl_up_sync(0xffffffffu, xi_y, 1);
            float nx2 = __shfl_up_sync(0xffffffffu, xi_z, 1);
            float nv0 = __shfl_up_sync(0xffffffffu, vi_x, 1);
            float nv1 = __shfl_up_sync(0xffffffffu, vi_y, 1);
            float nv2 = __shfl_up_sync(0xffffffffu, vi_z, 1);
            if (sec) {
                xi_x = nx0; xi_y = nx1; xi_z = nx2;
                vi_x = nv0; vi_y = nv1; vi_z = nv2;
            }
        }

        if (owner)                                   // coalesced slot-order store
            nxt[slot] = make_float4(xi_x, xi_y, xi_z,
                                    __uint_as_float(pack_v(vi_x, vi_y, vi_z)));

        if (step + 1 < NSTEP) {
            grid_sync();
            const float4* t = cur; cur = nxt; nxt = (float4*)t;
        }
    }

    if (owner) {
        out[3*v+0] = xi_x;
        out[3*v+1] = xi_y;
        out[3*v+2] = xi_z;
    }
}

// ---------------- launch ----------------------------------------------------
extern "C" void kernel_launch(void* const* d_in, const int* in_sizes, int n_in,
                              void* d_out, int out_size) {
    const float* x0   = (const float*)d_in[0];   // [N_V, 3] f32
    const int2*  sp   = (const int2*) d_in[1];   // [N_S, 2] i32
    const float* rest = (const float*)d_in[2];   // [N_S]    f32
    const float* mass = (const float*)d_in[3];   // [N_V]    f32
    float*       out  = (float*)d_out;

    const size_t smem = (size_t)CAP_EDGES * sizeof(int2);
    cudaFuncSetAttribute(k_sim, cudaFuncAttributeMaxDynamicSharedMemorySize, (int)smem);

    const int TB = 256;
    k_clear     <<<(N_VP + TB - 1) / TB, TB>>>();
    k_count     <<<(N_S / 2 + TB - 1) / TB, TB>>>((const int4*)sp);
    k_hist      <<<(N_V + TB - 1) / TB, TB>>>();
    k_scan_bins <<<1, 1024>>>();
    k_scatter   <<<(N_V + TB - 1) / TB, TB>>>();
    k_wdeg      <<<(NWARP + TB - 1) / TB, TB>>>();
    k_scan_warps<<<1, 1024>>>();
    k_vbase     <<<(N_V + TB - 1) / TB, TB>>>();
    k_fill      <<<(N_S + TB - 1) / TB, TB>>>(sp, rest);
    k_init      <<<(N_V + TB - 1) / TB, TB>>>(x0, mass);
    k_sim       <<<NBLK, NTHR, smem>>>(out);
}